// round 9
// baseline (speedup 1.0000x reference)
#include <cuda_runtime.h>
#include <math.h>

#define TPB    288        // 9 warps
#define NPOS   289        // 17*17 core positions
#define TW     28         // padded tile width (27 rows x 28 cols)
#define TCELLS (27*28)
#define LG     21         // L grid is 21x21 per orientation
#define LSZ    (21*21)

typedef unsigned long long u64;

#define ADD2(d,a,b)   asm("add.rn.f32x2 %0,%1,%2;"    : "=l"(d) : "l"(a), "l"(b))
#define MUL2(d,a,b)   asm("mul.rn.f32x2 %0,%1,%2;"    : "=l"(d) : "l"(a), "l"(b))
#define FMA2(d,a,b,c) asm("fma.rn.f32x2 %0,%1,%2,%3;" : "=l"(d) : "l"(a), "l"(b), "l"(c))
#define UNPK2(x,y,a)  asm("mov.b64 {%0,%1},%2;"       : "=f"(x), "=f"(y) : "l"(a))
#define LG2(d,s)      asm("lg2.approx.f32 %0,%1;"     : "=f"(d) : "f"(s))
#define EX2(d,s)      asm("ex2.approx.f32 %0,%1;"     : "=f"(d) : "f"(s))

// s^(5/6); s==0 -> lg2=-Inf -> ex2=0 (matches guarded ref)
__device__ __forceinline__ float pow56(float s) {
    float l, r; LG2(l, s); l *= 0.8333333333f; EX2(r, l); return r;
}
// (sd/32)^(1/5) = exp2(0.2*log2(sd) - 1); sd==0 -> 0
__device__ __forceinline__ float pow15_div32(float sd) {
    float l, r; LG2(l, sd); l = fmaf(0.2f, l, -1.0f); EX2(r, l); return r;
}

// packed (s0,s1) = sum over the 5 windows of (2*relu(L+NC))^6, from precomputed L
template<int LS>
__device__ __forceinline__ u64 orientL(const float2* __restrict__ L, int cell, u64 NC)
{
    const u64 AMSK = 0x7FFFFFFF7FFFFFFFULL;
    u64 S = 0ULL;
    #pragma unroll
    for (int k = -2; k <= 2; ++k) {
        u64 Lv = *(const u64*)&L[cell + k * LS];
        u64 R;  ADD2(R, Lv, NC);             // r = window_sum - 6*center (both streams)
        u64 A = R & AMSK;                    // |r|
        u64 T;  ADD2(T, R, A);               // 2*relu(r), exact
        u64 T2; MUL2(T2, T, T);
        u64 T4; MUL2(T4, T2, T2);
        FMA2(S, T4, T2, S);                  // += (2relu)^6 = 64*relu^6
    }
    return S;
}

__global__ __launch_bounds__(TPB, 7)
void topo_kernel(const float* __restrict__ state, float* __restrict__ out, int nb)
{
    const int b   = blockIdx.x;
    const int tid = threadIdx.x;

    __shared__ float2 g[TCELLS];                       // channel-combined, zero halo
    __shared__ float2 Lh[LSZ], Lv[LSZ], Ld[LSZ], La[LSZ];  // 5-cell line sums per orientation
    __shared__ float2 ncs[NPOS];                       // (-6x0,-6x1) for core positions
    __shared__ float  red[64];

    // phase 0a: zero-halo combined tile
    for (int i = tid; i < TCELLS; i += TPB) g[i] = make_float2(0.f, 0.f);
    __syncthreads();

    // phase 0b: load 19x19x3 NHWC, fold channels
    const float* sp = state + (size_t)b * 1083;
    for (int i = tid; i < 361; i += TPB) {
        int y = i / 19, x = i - y * 19;
        float x0 = sp[3 * i], x1 = sp[3 * i + 1], x2 = sp[3 * i + 2];
        g[(y + 4) * TW + (x + 4)] =
            make_float2(fmaf(-5.f, x1 + x2, x0), fmaf(-5.f, x0 + x2, x1));
        if (y >= 1 && y <= 17 && x >= 1 && x <= 17)
            ncs[(y - 1) * 17 + (x - 1)] = make_float2(-6.f * x0, -6.f * x1);
    }
    __syncthreads();

    // phase 1: L_o(c) = sum of g over 5-cell line centered at c, for 21x21 cells
    for (int c = tid; c < LSZ; c += TPB) {
        int gr = c / LG, gc = c - gr * LG;
        int tb = (gr + 3) * TW + (gc + 3);
        u64 ctr = *(const u64*)&g[tb];
        #define LSUM(dst, st) { \
            u64 pa, pb, s; \
            ADD2(pa, *(const u64*)&g[tb - 2*(st)], *(const u64*)&g[tb - (st)]); \
            ADD2(pb, *(const u64*)&g[tb + (st)],   *(const u64*)&g[tb + 2*(st)]); \
            ADD2(pa, pa, pb); ADD2(s, pa, ctr); \
            *(u64*)&dst[c] = s; }
        LSUM(Lh, 1) LSUM(Lv, TW) LSUM(Ld, TW + 1) LSUM(La, TW - 1)
        #undef LSUM
    }
    __syncthreads();

    // phase 2: per-position power sums from L
    const int py = tid / 17;
    const int px = tid - py * 17;
    const int cell = (py + 2) * LG + (px + 2);

    float logit, dval;
    {
        const u64 NC = *(const u64*)&ncs[tid];
        u64 S; float s0, s1, sd0, sd1;
        S = orientL<1>(Lh, cell, NC);   UNPK2(s0, s1, S); sd0  = pow56(s0); sd1  = pow56(s1);
        S = orientL<LG>(Lv, cell, NC);  UNPK2(s0, s1, S); sd0 += pow56(s0); sd1 += pow56(s1);
        S = orientL<LG+1>(Ld, cell, NC);UNPK2(s0, s1, S); sd0 += pow56(s0); sd1 += pow56(s1);
        S = orientL<LG-1>(La, cell, NC);UNPK2(s0, s1, S); sd0 += pow56(s0); sd1 += pow56(s1);
        float f0 = pow15_div32(sd0);
        float f1 = pow15_div32(sd1);
        logit = f0 + f1;
        dval  = f0 - f1;
    }

    const unsigned FULL = 0xffffffffu;
    const int wid  = tid >> 5;
    const int lane = tid & 31;

    // position 288 (py=px=16): one orientation each on lane 0 of warps 0..3
    if (lane == 0 && wid < 4) {
        const int c2 = 18 * LG + 18;
        const u64 NC2 = *(const u64*)&ncs[288];
        u64 S;
        if      (wid == 0) S = orientL<1>(Lh, c2, NC2);
        else if (wid == 1) S = orientL<LG>(Lv, c2, NC2);
        else if (wid == 2) S = orientL<LG+1>(Ld, c2, NC2);
        else               S = orientL<LG-1>(La, c2, NC2);
        float s0, s1; UNPK2(s0, s1, S);
        red[40 + 2 * wid]     = pow56(s0);
        red[40 + 2 * wid + 1] = pow56(s1);
    }

    // block max of logits
    float m = logit;
    #pragma unroll
    for (int off = 16; off; off >>= 1)
        m = fmaxf(m, __shfl_xor_sync(FULL, m, off));
    if (lane == 0) red[wid] = m;
    __syncthreads();

    float logit2 = -INFINITY, dval2 = 0.f;   // assembled by tid 0
    if (tid < 32) {
        float t = (tid < TPB / 32) ? red[tid] : -INFINITY;
        if (tid == 0) {
            float sd0 = (red[40] + red[42]) + (red[44] + red[46]);
            float sd1 = (red[41] + red[43]) + (red[45] + red[47]);
            float f0 = pow15_div32(sd0);
            float f1 = pow15_div32(sd1);
            logit2 = f0 + f1;
            dval2  = f0 - f1;
            t = fmaxf(t, logit2);
        }
        #pragma unroll
        for (int off = 8; off; off >>= 1)
            t = fmaxf(t, __shfl_xor_sync(FULL, t, off));
        if (tid == 0) red[32] = t;
    }
    __syncthreads();
    const float maxv = red[32];

    // softmax denom + value-head sum
    float e  = __expf(2.f * (logit - maxv));                 // POLICY_STRETCH = 2
    float e2 = (tid == 0) ? __expf(2.f * (logit2 - maxv)) : 0.f;
    float se = e + e2, sv = dval + dval2;
    #pragma unroll
    for (int off = 16; off; off >>= 1) {
        se += __shfl_xor_sync(FULL, se, off);
        sv += __shfl_xor_sync(FULL, sv, off);
    }
    if (lane == 0) { red[wid] = se; red[wid + 16] = sv; }
    __syncthreads();
    if (tid < 32) {
        float a  = (tid < TPB / 32) ? red[tid] : 0.f;
        float bb = (tid < TPB / 32) ? red[tid + 16] : 0.f;
        #pragma unroll
        for (int off = 8; off; off >>= 1) {
            a  += __shfl_xor_sync(FULL, a, off);
            bb += __shfl_xor_sync(FULL, bb, off);
        }
        if (tid == 0) { red[33] = a; red[34] = bb; }
    }
    __syncthreads();

    const float denom = red[33];
    out[(size_t)b * NPOS + tid] = __fdividef(e, denom);
    if (tid == 0) {
        out[(size_t)b * NPOS + 288] = __fdividef(e2, denom);
        out[(size_t)nb * NPOS + b]  = tanhf(red[34] * (0.2f / 32.f)); // tanh(VS*VG*D)
    }
}

extern "C" void kernel_launch(void* const* d_in, const int* in_sizes, int n_in,
                              void* d_out, int out_size)
{
    const float* state = (const float*)d_in[0];
    const int nb = in_sizes[0] / (19 * 19 * 3);
    topo_kernel<<<nb, TPB>>>(state, (float*)d_out, nb);
}

// round 10
// speedup vs baseline: 1.0410x; 1.0410x over previous
#include <cuda_runtime.h>
#include <math.h>

#define TPB    96         // 3 warps; each thread computes 3 positions
#define NPOS   289        // 17*17 core positions
#define TW     28         // padded tile width (27 rows x 28 cols)
#define TCELLS (27*28)

typedef unsigned long long u64;

#define ADD2(d,a,b)   asm("add.rn.f32x2 %0,%1,%2;"    : "=l"(d) : "l"(a), "l"(b))
#define MUL2(d,a,b)   asm("mul.rn.f32x2 %0,%1,%2;"    : "=l"(d) : "l"(a), "l"(b))
#define FMA2(d,a,b,c) asm("fma.rn.f32x2 %0,%1,%2,%3;" : "=l"(d) : "l"(a), "l"(b), "l"(c))
#define UNPK2(x,y,a)  asm("mov.b64 {%0,%1},%2;"       : "=f"(x), "=f"(y) : "l"(a))
#define LG2(d,s)      asm("lg2.approx.f32 %0,%1;"     : "=f"(d) : "f"(s))
#define EX2(d,s)      asm("ex2.approx.f32 %0,%1;"     : "=f"(d) : "f"(s))
#define TANH(d,s)     asm("tanh.approx.f32 %0,%1;"    : "=f"(d) : "f"(s))

// s^(5/6); s==0 -> lg2=-Inf -> ex2=0 (matches guarded ref)
__device__ __forceinline__ float pow56(float s) {
    float l, r; LG2(l, s); l *= 0.8333333333f; EX2(r, l); return r;
}
// (sd/32)^(1/5) = exp2(0.2*log2(sd) - 1); sd==0 -> 0
__device__ __forceinline__ float pow15_div32(float sd) {
    float l, r; LG2(l, sd); l = fmaf(0.2f, l, -1.0f); EX2(r, l); return r;
}

// one orientation: packed (s0,s1) = sum over 5 windows of (2*relu(r))^6
// st may be compile-time (unrolled main path) or runtime (position-288 path)
__device__ __forceinline__ u64 orient_S(const float2* __restrict__ g,
                                        int base, int st, u64 NC, u64 Dc)
{
    const u64 NEG1 = 0xBF800000BF800000ULL;
    const u64 AMSK = 0x7FFFFFFF7FFFFFFFULL;

    u64 D0 = *(const u64*)&g[base - 4 * st];
    u64 D1 = *(const u64*)&g[base - 3 * st];
    u64 D2 = *(const u64*)&g[base - 2 * st];
    u64 D3 = *(const u64*)&g[base - 1 * st];
    u64 D5 = *(const u64*)&g[base + 1 * st];
    u64 D6 = *(const u64*)&g[base + 2 * st];
    u64 D7 = *(const u64*)&g[base + 3 * st];
    u64 D8 = *(const u64*)&g[base + 4 * st];

    u64 pa, pb, R0;
    ADD2(pa, Dc, D5); ADD2(pb, D6, D7); ADD2(pa, pa, pb); ADD2(pa, pa, D8);
    ADD2(R0, pa, NC);
    u64 qa, qb, R4;
    ADD2(qa, D0, D1); ADD2(qb, D2, D3); ADD2(qa, qa, qb); ADD2(qa, qa, Dc);
    ADD2(R4, qa, NC);
    u64 R1, R2, R3;
    ADD2(R1, R0, D3); FMA2(R1, D8, NEG1, R1);
    ADD2(R2, R1, D2); FMA2(R2, D7, NEG1, R2);
    ADD2(R3, R4, D5); FMA2(R3, D0, NEG1, R3);

    u64 S = 0ULL;
    #define QSTEP(R) { u64 A = (R) & AMSK; u64 T; ADD2(T, R, A); \
                       u64 T2; MUL2(T2, T, T); u64 T4; MUL2(T4, T2, T2); \
                       FMA2(S, T4, T2, S); }
    QSTEP(R0) QSTEP(R1) QSTEP(R2) QSTEP(R3) QSTEP(R4)
    #undef QSTEP
    return S;
}

__global__ __launch_bounds__(TPB, 20)
void topo_kernel(const float* __restrict__ state, float* __restrict__ out, int nb)
{
    const int b   = blockIdx.x;
    const int tid = threadIdx.x;

    __shared__ float2 g[TCELLS];     // channel-combined, zero halo
    __shared__ float2 ncs[NPOS];     // (-6x0,-6x1) per core position
    __shared__ float  slog[NPOS];    // logits (frees registers)
    __shared__ float  red[32];

    for (int i = tid; i < TCELLS; i += TPB) g[i] = make_float2(0.f, 0.f);
    __syncthreads();

    const float* sp = state + (size_t)b * 1083;
    for (int i = tid; i < 361; i += TPB) {
        int y = i / 19, x = i - y * 19;
        float x0 = sp[3 * i], x1 = sp[3 * i + 1], x2 = sp[3 * i + 2];
        g[(y + 4) * TW + (x + 4)] =
            make_float2(fmaf(-5.f, x1 + x2, x0), fmaf(-5.f, x0 + x2, x1));
        if (y >= 1 && y <= 17 && x >= 1 && x <= 17)
            ncs[(y - 1) * 17 + (x - 1)] = make_float2(-6.f * x0, -6.f * x1);
    }
    __syncthreads();

    // ---- phase 2: 3 positions per thread ----
    float lmax = -INFINITY;
    float svloc = 0.f;
    #pragma unroll
    for (int k = 0; k < 3; ++k) {
        const int p  = tid * 3 + k;          // 0..287
        const int py = p / 17;
        const int px = p - py * 17;
        const int base = (py + 5) * TW + (px + 5);
        const u64 NC = *(const u64*)&ncs[p];
        const u64 Dc = *(const u64*)&g[base];

        u64 S; float s0, s1, sd0, sd1;
        S = orient_S(g, base, 1, NC, Dc);      UNPK2(s0, s1, S); sd0  = pow56(s0); sd1  = pow56(s1);
        S = orient_S(g, base, TW, NC, Dc);     UNPK2(s0, s1, S); sd0 += pow56(s0); sd1 += pow56(s1);
        S = orient_S(g, base, TW + 1, NC, Dc); UNPK2(s0, s1, S); sd0 += pow56(s0); sd1 += pow56(s1);
        S = orient_S(g, base, TW - 1, NC, Dc); UNPK2(s0, s1, S); sd0 += pow56(s0); sd1 += pow56(s1);

        float f0 = pow15_div32(sd0);
        float f1 = pow15_div32(sd1);
        float lg = f0 + f1;
        slog[p] = lg;
        svloc  += f0 - f1;
        lmax    = fmaxf(lmax, lg);
    }

    // position 288: one orientation per thread on tids 0..3 (uniform code, runtime stride)
    if (tid < 4) {
        const int b2 = 21 * TW + 21;
        const int st = (tid == 0) ? 1 : (tid == 1) ? TW : (tid == 2) ? TW + 1 : TW - 1;
        const u64 NC2 = *(const u64*)&ncs[288];
        const u64 Dc2 = *(const u64*)&g[b2];
        u64 S = orient_S(g, b2, st, NC2, Dc2);
        float s0, s1; UNPK2(s0, s1, S);
        red[24 + 2 * tid]     = pow56(s0);
        red[25 + 2 * tid]     = pow56(s1);
    }
    __syncthreads();

    const unsigned FULL = 0xffffffffu;
    const int wid  = tid >> 5;
    const int lane = tid & 31;

    float logit2 = -INFINITY, e2 = 0.f;
    if (tid == 0) {
        float sd0 = (red[24] + red[26]) + (red[28] + red[30]);
        float sd1 = (red[25] + red[27]) + (red[29] + red[31]);
        float f0 = pow15_div32(sd0);
        float f1 = pow15_div32(sd1);
        logit2 = f0 + f1;
        svloc += f0 - f1;
        lmax   = fmaxf(lmax, logit2);
    }

    // block max: warp tree + 3-slot combine
    float m = lmax;
    #pragma unroll
    for (int off = 16; off; off >>= 1)
        m = fmaxf(m, __shfl_xor_sync(FULL, m, off));
    if (lane == 0) red[wid] = m;
    __syncthreads();
    const float maxv = fmaxf(fmaxf(red[0], red[1]), red[2]);

    // exp(2*(l - maxv)) = ex2(2.885390*(l - maxv))
    const float C = 2.8853900817779268f;
    float e0, e1v, e2v;
    { float t0 = slog[tid * 3 + 0], t1 = slog[tid * 3 + 1], t2 = slog[tid * 3 + 2];
      EX2(e0,  C * (t0 - maxv));
      EX2(e1v, C * (t1 - maxv));
      EX2(e2v, C * (t2 - maxv)); }
    if (tid == 0) EX2(e2, C * (logit2 - maxv));

    float se = e0 + e1v + e2v + e2;
    float sv = svloc;
    #pragma unroll
    for (int off = 16; off; off >>= 1) {
        se += __shfl_xor_sync(FULL, se, off);
        sv += __shfl_xor_sync(FULL, sv, off);
    }
    if (lane == 0) { red[8 + wid] = se; red[16 + wid] = sv; }
    __syncthreads();

    const float denom = (red[8] + red[9]) + red[10];
    const float rden  = __frcp_rn(denom);

    float* op = out + (size_t)b * NPOS + tid * 3;
    op[0] = e0 * rden; op[1] = e1v * rden; op[2] = e2v * rden;
    if (tid == 0) {
        out[(size_t)b * NPOS + 288] = e2 * rden;
        float vs = ((red[16] + red[17]) + red[18]) * 0.00625f;  // VS*VG = 0.2/32
        float tv; TANH(tv, vs);
        out[(size_t)nb * NPOS + b] = tv;
    }
}

extern "C" void kernel_launch(void* const* d_in, const int* in_sizes, int n_in,
                              void* d_out, int out_size)
{
    const float* state = (const float*)d_in[0];
    const int nb = in_sizes[0] / (19 * 19 * 3);
    topo_kernel<<<nb, TPB>>>(state, (float*)d_out, nb);
}

// round 11
// speedup vs baseline: 1.1976x; 1.1504x over previous
#include <cuda_runtime.h>
#include <math.h>

#define TPB    288        // 9 warps
#define NPOS   289        // 17*17 core positions
#define TW     29         // padded tile width (27 rows x 29 cols) — bank-friendly stride
#define TCELLS (27*TW)

typedef unsigned long long u64;

#define ADD2(d,a,b)   asm("add.rn.f32x2 %0,%1,%2;"    : "=l"(d) : "l"(a), "l"(b))
#define MUL2(d,a,b)   asm("mul.rn.f32x2 %0,%1,%2;"    : "=l"(d) : "l"(a), "l"(b))
#define FMA2(d,a,b,c) asm("fma.rn.f32x2 %0,%1,%2,%3;" : "=l"(d) : "l"(a), "l"(b), "l"(c))
#define UNPK2(x,y,a)  asm("mov.b64 {%0,%1},%2;"       : "=f"(x), "=f"(y) : "l"(a))
#define LG2(d,s)      asm("lg2.approx.f32 %0,%1;"     : "=f"(d) : "f"(s))
#define EX2(d,s)      asm("ex2.approx.f32 %0,%1;"     : "=f"(d) : "f"(s))

// s^(5/6); s==0 -> lg2=-Inf -> ex2=0 (matches guarded ref)
__device__ __forceinline__ float pow56(float s) {
    float l, r; LG2(l, s); l *= 0.8333333333f; EX2(r, l); return r;
}
// (sd/32)^(1/5) = exp2(0.2*log2(sd) - 1); sd==0 -> 0
__device__ __forceinline__ float pow15_div32(float sd) {
    float l, r; LG2(l, sd); l = fmaf(0.2f, l, -1.0f); EX2(r, l); return r;
}

// one orientation: packed (s0,s1) = sum over 5 windows of (2*relu(r))^6
__device__ __forceinline__ u64 orient_S(const float2* __restrict__ g,
                                        int base, int st, u64 NC, u64 Dc)
{
    const u64 NEG1 = 0xBF800000BF800000ULL;
    const u64 AMSK = 0x7FFFFFFF7FFFFFFFULL;

    u64 D0 = *(const u64*)&g[base - 4 * st];
    u64 D1 = *(const u64*)&g[base - 3 * st];
    u64 D2 = *(const u64*)&g[base - 2 * st];
    u64 D3 = *(const u64*)&g[base - 1 * st];
    u64 D5 = *(const u64*)&g[base + 1 * st];
    u64 D6 = *(const u64*)&g[base + 2 * st];
    u64 D7 = *(const u64*)&g[base + 3 * st];
    u64 D8 = *(const u64*)&g[base + 4 * st];

    u64 pa, pb, R0;
    ADD2(pa, Dc, D5); ADD2(pb, D6, D7); ADD2(pa, pa, pb); ADD2(pa, pa, D8);
    ADD2(R0, pa, NC);
    u64 qa, qb, R4;
    ADD2(qa, D0, D1); ADD2(qb, D2, D3); ADD2(qa, qa, qb); ADD2(qa, qa, Dc);
    ADD2(R4, qa, NC);
    u64 R1, R2, R3;
    ADD2(R1, R0, D3); FMA2(R1, D8, NEG1, R1);
    ADD2(R2, R1, D2); FMA2(R2, D7, NEG1, R2);
    ADD2(R3, R4, D5); FMA2(R3, D0, NEG1, R3);

    u64 S = 0ULL;
    #define QSTEP(R) { u64 A = (R) & AMSK; u64 T; ADD2(T, R, A); \
                       u64 T2; MUL2(T2, T, T); u64 T4; MUL2(T4, T2, T2); \
                       FMA2(S, T4, T2, S); }
    QSTEP(R0) QSTEP(R1) QSTEP(R2) QSTEP(R3) QSTEP(R4)
    #undef QSTEP
    return S;
}

__global__ __launch_bounds__(TPB, 7)
void topo_kernel(const float* __restrict__ state, float* __restrict__ out, int nb)
{
    const int b   = blockIdx.x;
    const int tid = threadIdx.x;

    __shared__ float2 g[TCELLS];     // channel-combined, zero halo
    __shared__ float2 ncs[NPOS];     // (-6x0,-6x1) per core position
    __shared__ float  red[64];

    for (int i = tid; i < TCELLS; i += TPB) g[i] = make_float2(0.f, 0.f);
    __syncthreads();

    const float* sp = state + (size_t)b * 1083;
    for (int i = tid; i < 361; i += TPB) {
        int y = i / 19, x = i - y * 19;
        float x0 = sp[3 * i], x1 = sp[3 * i + 1], x2 = sp[3 * i + 2];
        g[(y + 4) * TW + (x + 4)] =
            make_float2(fmaf(-5.f, x1 + x2, x0), fmaf(-5.f, x0 + x2, x1));
        if (y >= 1 && y <= 17 && x >= 1 && x <= 17)
            ncs[(y - 1) * 17 + (x - 1)] = make_float2(-6.f * x0, -6.f * x1);
    }
    __syncthreads();

    // conflict-free lane->position mapping:
    //   tid <  272 : (py, px) = (tid>>4, tid&15)   -> warps cover 2x 128B chunks
    //   tid >= 272 : px = 16, py = tid-272         -> column, stride 232B (no conflicts at TW=29)
    int py, px;
    if (tid < 272) { py = tid >> 4;  px = tid & 15; }
    else           { py = tid - 272; px = 16; }
    const int p    = py * 17 + px;              // logical position index 0..287
    const int base = (py + 5) * TW + (px + 5);
    const int steps[4] = {1, TW, TW + 1, TW - 1};   // H, V, diag, anti-diag

    float logit, dval;
    {
        const u64 NC = *(const u64*)&ncs[p];
        const u64 Dc = *(const u64*)&g[base];
        float sd0 = 0.f, sd1 = 0.f;
        #pragma unroll
        for (int o = 0; o < 4; ++o) {
            u64 S = orient_S(g, base, steps[o], NC, Dc);
            float s0, s1; UNPK2(s0, s1, S);
            sd0 += pow56(s0);
            sd1 += pow56(s1);
        }
        float f0 = pow15_div32(sd0);
        float f1 = pow15_div32(sd1);
        logit = f0 + f1;
        dval  = f0 - f1;
    }

    const unsigned FULL = 0xffffffffu;
    const int wid  = tid >> 5;
    const int lane = tid & 31;

    // position 288 (py=px=16): one orientation each on lane 0 of warps 0..3
    if (lane == 0 && wid < 4) {
        const int b2 = 21 * TW + 21;
        const u64 NC2 = *(const u64*)&ncs[288];
        const u64 Dc2 = *(const u64*)&g[b2];
        u64 S = orient_S(g, b2, steps[wid], NC2, Dc2);
        float s0, s1; UNPK2(s0, s1, S);
        red[40 + 2 * wid]     = pow56(s0);
        red[40 + 2 * wid + 1] = pow56(s1);
    }

    // block max of logits
    float m = logit;
    #pragma unroll
    for (int off = 16; off; off >>= 1)
        m = fmaxf(m, __shfl_xor_sync(FULL, m, off));
    if (lane == 0) red[wid] = m;
    __syncthreads();

    float logit2 = -INFINITY, dval2 = 0.f;   // assembled by tid 0
    if (tid < 32) {
        float t = (tid < TPB / 32) ? red[tid] : -INFINITY;
        if (tid == 0) {
            float sd0 = (red[40] + red[42]) + (red[44] + red[46]);
            float sd1 = (red[41] + red[43]) + (red[45] + red[47]);
            float f0 = pow15_div32(sd0);
            float f1 = pow15_div32(sd1);
            logit2 = f0 + f1;
            dval2  = f0 - f1;
            t = fmaxf(t, logit2);
        }
        #pragma unroll
        for (int off = 8; off; off >>= 1)
            t = fmaxf(t, __shfl_xor_sync(FULL, t, off));
        if (tid == 0) red[32] = t;
    }
    __syncthreads();
    const float maxv = red[32];

    // softmax denom + value-head sum
    float e  = __expf(2.f * (logit - maxv));                 // POLICY_STRETCH = 2
    float e2 = (tid == 0) ? __expf(2.f * (logit2 - maxv)) : 0.f;
    float se = e + e2, sv = dval + dval2;
    #pragma unroll
    for (int off = 16; off; off >>= 1) {
        se += __shfl_xor_sync(FULL, se, off);
        sv += __shfl_xor_sync(FULL, sv, off);
    }
    if (lane == 0) { red[wid] = se; red[wid + 16] = sv; }
    __syncthreads();
    if (tid < 32) {
        float a  = (tid < TPB / 32) ? red[tid] : 0.f;
        float bb = (tid < TPB / 32) ? red[tid + 16] : 0.f;
        #pragma unroll
        for (int off = 8; off; off >>= 1) {
            a  += __shfl_xor_sync(FULL, a, off);
            bb += __shfl_xor_sync(FULL, bb, off);
        }
        if (tid == 0) { red[33] = a; red[34] = bb; }
    }
    __syncthreads();

    const float denom = red[33];
    out[(size_t)b * NPOS + p] = __fdividef(e, denom);
    if (tid == 0) {
        out[(size_t)b * NPOS + 288] = __fdividef(e2, denom);
        out[(size_t)nb * NPOS + b]  = tanhf(red[34] * (0.2f / 32.f)); // tanh(VS*VG*D)
    }
}

extern "C" void kernel_launch(void* const* d_in, const int* in_sizes, int n_in,
                              void* d_out, int out_size)
{
    const float* state = (const float*)d_in[0];
    const int nb = in_sizes[0] / (19 * 19 * 3);
    topo_kernel<<<nb, TPB>>>(state, (float*)d_out, nb);
}

// round 12
// speedup vs baseline: 1.2540x; 1.0471x over previous
#include <cuda_runtime.h>
#include <math.h>

#define TPB    288        // 9 warps
#define NPOS   289        // 17*17 core positions
#define TW     29         // padded tile width (27 rows x 29 cols) — bank-friendly stride
#define TCELLS (27*TW)

typedef unsigned long long u64;

#define ADD2(d,a,b)   asm("add.rn.f32x2 %0,%1,%2;"    : "=l"(d) : "l"(a), "l"(b))
#define MUL2(d,a,b)   asm("mul.rn.f32x2 %0,%1,%2;"    : "=l"(d) : "l"(a), "l"(b))
#define FMA2(d,a,b,c) asm("fma.rn.f32x2 %0,%1,%2,%3;" : "=l"(d) : "l"(a), "l"(b), "l"(c))
#define UNPK2(x,y,a)  asm("mov.b64 {%0,%1},%2;"       : "=f"(x), "=f"(y) : "l"(a))
#define LG2(d,s)      asm("lg2.approx.f32 %0,%1;"     : "=f"(d) : "f"(s))
#define EX2(d,s)      asm("ex2.approx.f32 %0,%1;"     : "=f"(d) : "f"(s))

// s^(5/6); s==0 -> lg2=-Inf -> ex2=0 (matches guarded ref)
__device__ __forceinline__ float pow56(float s) {
    float l, r; LG2(l, s); l *= 0.8333333333f; EX2(r, l); return r;
}
// (sd/32)^(1/5) = exp2(0.2*log2(sd) - 1); sd==0 -> 0
__device__ __forceinline__ float pow15_div32(float sd) {
    float l, r; LG2(l, sd); l = fmaf(0.2f, l, -1.0f); EX2(r, l); return r;
}

// one orientation: packed (s0,s1) = sum over 5 windows of (2*relu(r))^6
// center-out build: 13 packed ops for all 5 windows (NC folded once)
__device__ __forceinline__ u64 orient_S(const float2* __restrict__ g,
                                        int base, int st, u64 NC, u64 Dc)
{
    const u64 NEG1 = 0xBF800000BF800000ULL;
    const u64 AMSK = 0x7FFFFFFF7FFFFFFFULL;

    u64 D0 = *(const u64*)&g[base - 4 * st];
    u64 D1 = *(const u64*)&g[base - 3 * st];
    u64 D2 = *(const u64*)&g[base - 2 * st];
    u64 D3 = *(const u64*)&g[base - 1 * st];
    u64 D5 = *(const u64*)&g[base + 1 * st];
    u64 D6 = *(const u64*)&g[base + 2 * st];
    u64 D7 = *(const u64*)&g[base + 3 * st];
    u64 D8 = *(const u64*)&g[base + 4 * st];

    // R2 = d2+d3+d4+d5+d6 + NC  (window q=2), tree + NC = 5 ops
    u64 pa, pb, R2;
    ADD2(pa, D2, D3); ADD2(pb, Dc, D5); ADD2(pa, pa, pb); ADD2(pa, pa, D6);
    ADD2(R2, pa, NC);
    // slides outward, 2 ops each
    u64 R0, R1, R3, R4;
    ADD2(R1, R2, D7); FMA2(R1, D2, NEG1, R1);   // q=1: 3..7
    ADD2(R0, R1, D8); FMA2(R0, D3, NEG1, R0);   // q=0: 4..8
    ADD2(R3, R2, D1); FMA2(R3, D6, NEG1, R3);   // q=3: 1..5
    ADD2(R4, R3, D0); FMA2(R4, D5, NEG1, R4);   // q=4: 0..4

    u64 S = 0ULL;
    #define QSTEP(R) { u64 A = (R) & AMSK; u64 T; ADD2(T, R, A); \
                       u64 T2; MUL2(T2, T, T); u64 T4; MUL2(T4, T2, T2); \
                       FMA2(S, T4, T2, S); }
    QSTEP(R0) QSTEP(R1) QSTEP(R2) QSTEP(R3) QSTEP(R4)
    #undef QSTEP
    return S;
}

__global__ __launch_bounds__(TPB, 7)
void topo_kernel(const float* __restrict__ state, float* __restrict__ out, int nb)
{
    const int b   = blockIdx.x;
    const int tid = threadIdx.x;

    __shared__ float2 g[TCELLS];     // channel-combined, zero halo
    __shared__ float2 nc6[361];      // (-6x0,-6x1) on the raw 19x19 grid
    __shared__ float  red[64];

    for (int i = tid; i < TCELLS; i += TPB) g[i] = make_float2(0.f, 0.f);
    __syncthreads();

    const float* sp = state + (size_t)b * 1083;
    for (int i = tid; i < 361; i += TPB) {
        int y = i / 19, x = i - y * 19;
        float x0 = sp[3 * i], x1 = sp[3 * i + 1], x2 = sp[3 * i + 2];
        g[(y + 4) * TW + (x + 4)] =
            make_float2(fmaf(-5.f, x1 + x2, x0), fmaf(-5.f, x0 + x2, x1));
        nc6[i] = make_float2(-6.f * x0, -6.f * x1);
    }
    __syncthreads();

    // conflict-free lane->position mapping:
    //   tid <  272 : (py, px) = (tid>>4, tid&15)   -> warps cover 2x 128B chunks
    //   tid >= 272 : px = 16, py = tid-272         -> column, stride 232B (no conflicts)
    int py, px;
    if (tid < 272) { py = tid >> 4;  px = tid & 15; }
    else           { py = tid - 272; px = 16; }
    const int p    = py * 17 + px;               // logical position index 0..287
    const int base = (py + 5) * TW + (px + 5);
    const int steps[4] = {1, TW, TW + 1, TW - 1};   // H, V, diag, anti-diag

    float logit, dval;
    {
        const u64 NC = *(const u64*)&nc6[(py + 1) * 19 + (px + 1)];
        const u64 Dc = *(const u64*)&g[base];
        float sd0 = 0.f, sd1 = 0.f;
        #pragma unroll
        for (int o = 0; o < 4; ++o) {
            u64 S = orient_S(g, base, steps[o], NC, Dc);
            float s0, s1; UNPK2(s0, s1, S);
            sd0 += pow56(s0);
            sd1 += pow56(s1);
        }
        float f0 = pow15_div32(sd0);
        float f1 = pow15_div32(sd1);
        logit = f0 + f1;
        dval  = f0 - f1;
    }

    const unsigned FULL = 0xffffffffu;
    const int wid  = tid >> 5;
    const int lane = tid & 31;

    // position 288 (py=px=16): one orientation each on lane 0 of warps 0..3
    if (lane == 0 && wid < 4) {
        const int b2 = 21 * TW + 21;
        const u64 NC2 = *(const u64*)&nc6[17 * 19 + 17];
        const u64 Dc2 = *(const u64*)&g[b2];
        u64 S = orient_S(g, b2, steps[wid], NC2, Dc2);
        float s0, s1; UNPK2(s0, s1, S);
        red[40 + 2 * wid]     = pow56(s0);
        red[40 + 2 * wid + 1] = pow56(s1);
    }

    // block max of logits
    float m = logit;
    #pragma unroll
    for (int off = 16; off; off >>= 1)
        m = fmaxf(m, __shfl_xor_sync(FULL, m, off));
    if (lane == 0) red[wid] = m;
    __syncthreads();

    float logit2 = -INFINITY, dval2 = 0.f;   // assembled by tid 0
    if (tid < 32) {
        float t = (tid < TPB / 32) ? red[tid] : -INFINITY;
        if (tid == 0) {
            float sd0 = (red[40] + red[42]) + (red[44] + red[46]);
            float sd1 = (red[41] + red[43]) + (red[45] + red[47]);
            float f0 = pow15_div32(sd0);
            float f1 = pow15_div32(sd1);
            logit2 = f0 + f1;
            dval2  = f0 - f1;
            t = fmaxf(t, logit2);
        }
        #pragma unroll
        for (int off = 8; off; off >>= 1)
            t = fmaxf(t, __shfl_xor_sync(FULL, t, off));
        if (tid == 0) red[32] = t;
    }
    __syncthreads();
    const float maxv = red[32];

    // softmax denom + value-head sum
    float e  = __expf(2.f * (logit - maxv));                 // POLICY_STRETCH = 2
    float e2 = (tid == 0) ? __expf(2.f * (logit2 - maxv)) : 0.f;
    float se = e + e2, sv = dval + dval2;
    #pragma unroll
    for (int off = 16; off; off >>= 1) {
        se += __shfl_xor_sync(FULL, se, off);
        sv += __shfl_xor_sync(FULL, sv, off);
    }
    if (lane == 0) { red[wid] = se; red[wid + 16] = sv; }
    __syncthreads();
    if (tid < 32) {
        float a  = (tid < TPB / 32) ? red[tid] : 0.f;
        float bb = (tid < TPB / 32) ? red[tid + 16] : 0.f;
        #pragma unroll
        for (int off = 8; off; off >>= 1) {
            a  += __shfl_xor_sync(FULL, a, off);
            bb += __shfl_xor_sync(FULL, bb, off);
        }
        if (tid == 0) { red[33] = a; red[34] = bb; }
    }
    __syncthreads();

    const float denom = red[33];
    out[(size_t)b * NPOS + p] = __fdividef(e, denom);
    if (tid == 0) {
        out[(size_t)b * NPOS + 288] = __fdividef(e2, denom);
        out[(size_t)nb * NPOS + b]  = tanhf(red[34] * (0.2f / 32.f)); // tanh(VS*VG*D)
    }
}

extern "C" void kernel_launch(void* const* d_in, const int* in_sizes, int n_in,
                              void* d_out, int out_size)
{
    const float* state = (const float*)d_in[0];
    const int nb = in_sizes[0] / (19 * 19 * 3);
    topo_kernel<<<nb, TPB>>>(state, (float*)d_out, nb);
}

// round 15
// speedup vs baseline: 1.3916x; 1.1097x over previous
#include <cuda_runtime.h>
#include <math.h>

#define TPB    288        // 9 warps
#define NPOS   289        // 17*17 core positions
#define TW     29         // padded tile width (27 rows x 29 cols) — bank-friendly stride
#define TCELLS (27*TW)

typedef unsigned long long u64;

#define ADD2(d,a,b)   asm("add.rn.f32x2 %0,%1,%2;"    : "=l"(d) : "l"(a), "l"(b))
#define MUL2(d,a,b)   asm("mul.rn.f32x2 %0,%1,%2;"    : "=l"(d) : "l"(a), "l"(b))
#define FMA2(d,a,b,c) asm("fma.rn.f32x2 %0,%1,%2,%3;" : "=l"(d) : "l"(a), "l"(b), "l"(c))
#define UNPK2(x,y,a)  asm("mov.b64 {%0,%1},%2;"       : "=f"(x), "=f"(y) : "l"(a))
#define PACK2(d,x,y)  asm("mov.b64 %0,{%1,%2};"       : "=l"(d) : "f"(x), "f"(y))
#define LG2(d,s)      asm("lg2.approx.f32 %0,%1;"     : "=f"(d) : "f"(s))
#define EX2(d,s)      asm("ex2.approx.f32 %0,%1;"     : "=f"(d) : "f"(s))

// s^(5/6); s==0 -> lg2=-Inf -> ex2=0 (matches guarded ref)
__device__ __forceinline__ float pow56(float s) {
    float l, r; LG2(l, s); l *= 0.8333333333f; EX2(r, l); return r;
}
// sd^(1/5); sd==0 -> 0
__device__ __forceinline__ float pow15(float sd) {
    float l, r; LG2(l, sd); l *= 0.2f; EX2(r, l); return r;
}

// one orientation: packed (s0,s1) = sum over 5 windows of relu(r)^6
// center-out build: 13 packed ops for all 5 windows (NC folded once)
__device__ __forceinline__ u64 orient_S(const float2* __restrict__ g,
                                        int base, int st, u64 NC, u64 Dc)
{
    const u64 NEG1 = 0xBF800000BF800000ULL;

    u64 D0 = *(const u64*)&g[base - 4 * st];
    u64 D1 = *(const u64*)&g[base - 3 * st];
    u64 D2 = *(const u64*)&g[base - 2 * st];
    u64 D3 = *(const u64*)&g[base - 1 * st];
    u64 D5 = *(const u64*)&g[base + 1 * st];
    u64 D6 = *(const u64*)&g[base + 2 * st];
    u64 D7 = *(const u64*)&g[base + 3 * st];
    u64 D8 = *(const u64*)&g[base + 4 * st];

    // R2 = d2+d3+d4+d5+d6 + NC  (window q=2)
    u64 pa, pb, R2;
    ADD2(pa, D2, D3); ADD2(pb, Dc, D5); ADD2(pa, pa, pb); ADD2(pa, pa, D6);
    ADD2(R2, pa, NC);
    // slides outward, 2 ops each
    u64 R0, R1, R3, R4;
    ADD2(R1, R2, D7); FMA2(R1, D2, NEG1, R1);   // q=1: 3..7
    ADD2(R0, R1, D8); FMA2(R0, D3, NEG1, R0);   // q=0: 4..8
    ADD2(R3, R2, D1); FMA2(R3, D6, NEG1, R3);   // q=3: 1..5
    ADD2(R4, R3, D0); FMA2(R4, D5, NEG1, R4);   // q=4: 0..4

    u64 S = 0ULL;
    // relu per 32-bit half via FMNMX (alu pipe); halves are separate regs, pack/unpack coalesced
    #define QSTEP(R) { float qa, qb; UNPK2(qa, qb, R); \
                       qa = fmaxf(qa, 0.f); qb = fmaxf(qb, 0.f); \
                       u64 T; PACK2(T, qa, qb); \
                       u64 T2; MUL2(T2, T, T); u64 T4; MUL2(T4, T2, T2); \
                       FMA2(S, T4, T2, S); }
    QSTEP(R0) QSTEP(R1) QSTEP(R2) QSTEP(R3) QSTEP(R4)
    #undef QSTEP
    return S;
}

__global__ __launch_bounds__(TPB, 7)
void topo_kernel(const float* __restrict__ state, float* __restrict__ out, int nb)
{
    const int b   = blockIdx.x;
    const int tid = threadIdx.x;

    __shared__ float2 g[TCELLS];     // channel-combined, zero halo
    __shared__ float2 nc6[361];      // (-6x0,-6x1) on the raw 19x19 grid
    __shared__ float  red[64];

    for (int i = tid; i < TCELLS; i += TPB) g[i] = make_float2(0.f, 0.f);
    __syncthreads();

    const float* sp = state + (size_t)b * 1083;
    for (int i = tid; i < 361; i += TPB) {
        int y = i / 19, x = i - y * 19;
        float x0 = sp[3 * i], x1 = sp[3 * i + 1], x2 = sp[3 * i + 2];
        g[(y + 4) * TW + (x + 4)] =
            make_float2(fmaf(-5.f, x1 + x2, x0), fmaf(-5.f, x0 + x2, x1));
        nc6[i] = make_float2(-6.f * x0, -6.f * x1);
    }
    __syncthreads();

    // conflict-free lane->position mapping:
    //   tid <  272 : (py, px) = (tid>>4, tid&15)   -> warps cover 2x 128B chunks
    //   tid >= 272 : px = 16, py = tid-272         -> column, stride 232B (no conflicts)
    int py, px;
    if (tid < 272) { py = tid >> 4;  px = tid & 15; }
    else           { py = tid - 272; px = 16; }
    const int p    = py * 17 + px;               // logical position index 0..287
    const int base = (py + 5) * TW + (px + 5);
    const int steps[4] = {1, TW, TW + 1, TW - 1};   // H, V, diag, anti-diag

    float logit, dval;
    {
        const u64 NC = *(const u64*)&nc6[(py + 1) * 19 + (px + 1)];
        const u64 Dc = *(const u64*)&g[base];

        // two independent accumulator pairs -> shorter MUFU->add chains
        u64 Sa = orient_S(g, base, steps[0], NC, Dc);
        u64 Sb = orient_S(g, base, steps[1], NC, Dc);
        u64 Sc = orient_S(g, base, steps[2], NC, Dc);
        u64 Sd = orient_S(g, base, steps[3], NC, Dc);
        float a0, a1, b0, b1, c0, c1, d0, d1;
        UNPK2(a0, a1, Sa); UNPK2(b0, b1, Sb);
        UNPK2(c0, c1, Sc); UNPK2(d0, d1, Sd);
        float sd0 = (pow56(a0) + pow56(b0)) + (pow56(c0) + pow56(d0));
        float sd1 = (pow56(a1) + pow56(b1)) + (pow56(c1) + pow56(d1));
        float f0 = pow15(sd0);
        float f1 = pow15(sd1);
        logit = f0 + f1;
        dval  = f0 - f1;
    }

    const unsigned FULL = 0xffffffffu;
    const int wid  = tid >> 5;
    const int lane = tid & 31;

    // position 288 (py=px=16): one orientation each on lane 0 of warps 0..3
    if (lane == 0 && wid < 4) {
        const int b2 = 21 * TW + 21;
        const u64 NC2 = *(const u64*)&nc6[17 * 19 + 17];
        const u64 Dc2 = *(const u64*)&g[b2];
        u64 S = orient_S(g, b2, steps[wid], NC2, Dc2);
        float s0, s1; UNPK2(s0, s1, S);
        red[40 + 2 * wid]     = pow56(s0);
        red[40 + 2 * wid + 1] = pow56(s1);
    }

    // block max of logits
    float m = logit;
    #pragma unroll
    for (int off = 16; off; off >>= 1)
        m = fmaxf(m, __shfl_xor_sync(FULL, m, off));
    if (lane == 0) red[wid] = m;
    __syncthreads();

    float logit2 = -INFINITY, dval2 = 0.f;   // assembled by tid 0
    if (tid < 32) {
        float t = (tid < TPB / 32) ? red[tid] : -INFINITY;
        if (tid == 0) {
            float sd0 = (red[40] + red[42]) + (red[44] + red[46]);
            float sd1 = (red[41] + red[43]) + (red[45] + red[47]);
            float f0 = pow15(sd0);
            float f1 = pow15(sd1);
            logit2 = f0 + f1;
            dval2  = f0 - f1;
            t = fmaxf(t, logit2);
        }
        #pragma unroll
        for (int off = 8; off; off >>= 1)
            t = fmaxf(t, __shfl_xor_sync(FULL, t, off));
        if (tid == 0) red[32] = t;
    }
    __syncthreads();
    const float maxv = red[32];

    // exp(2*(l-maxv)) = ex2(C*(l-maxv)), C = 2*log2(e)
    const float C = 2.8853900817779268f;
    float e;  EX2(e,  C * (logit  - maxv));
    float e2 = 0.f;
    if (tid == 0) EX2(e2, C * (logit2 - maxv));

    float se = e + e2, sv = dval + dval2;
    #pragma unroll
    for (int off = 16; off; off >>= 1) {
        se += __shfl_xor_sync(FULL, se, off);
        sv += __shfl_xor_sync(FULL, sv, off);
    }
    if (lane == 0) { red[wid] = se; red[wid + 16] = sv; }
    __syncthreads();
    if (tid < 32) {
        float a  = (tid < TPB / 32) ? red[tid] : 0.f;
        float bb = (tid < TPB / 32) ? red[tid + 16] : 0.f;
        #pragma unroll
        for (int off = 8; off; off >>= 1) {
            a  += __shfl_xor_sync(FULL, a, off);
            bb += __shfl_xor_sync(FULL, bb, off);
        }
        if (tid == 0) { red[33] = a; red[34] = bb; }
    }
    __syncthreads();

    const float rden = __frcp_rn(red[33]);
    out[(size_t)b * NPOS + p] = e * rden;
    if (tid == 0) {
        out[(size_t)b * NPOS + 288] = e2 * rden;
        out[(size_t)nb * NPOS + b]  = tanhf(red[34] * (0.2f / 32.f)); // tanh(VS*VG*D)
    }
}

extern "C" void kernel_launch(void* const* d_in, const int* in_sizes, int n_in,
                              void* d_out, int out_size)
{
    const float* state = (const float*)d_in[0];
    const int nb = in_sizes[0] / (19 * 19 * 3);
    topo_kernel<<<nb, TPB>>>(state, (float*)d_out, nb);
}

// round 16
// speedup vs baseline: 1.3934x; 1.0013x over previous
#include <cuda_runtime.h>
#include <math.h>

#define TPB    288        // 9 warps
#define NPOS   289        // 17*17 core positions
#define TW     29         // padded tile width (27 rows x 29 cols) — bank-friendly stride
#define TCELLS (27*TW)

typedef unsigned long long u64;

#define ADD2(d,a,b)   asm("add.rn.f32x2 %0,%1,%2;"    : "=l"(d) : "l"(a), "l"(b))
#define MUL2(d,a,b)   asm("mul.rn.f32x2 %0,%1,%2;"    : "=l"(d) : "l"(a), "l"(b))
#define FMA2(d,a,b,c) asm("fma.rn.f32x2 %0,%1,%2,%3;" : "=l"(d) : "l"(a), "l"(b), "l"(c))
#define UNPK2(x,y,a)  asm("mov.b64 {%0,%1},%2;"       : "=f"(x), "=f"(y) : "l"(a))
#define PACK2(d,x,y)  asm("mov.b64 %0,{%1,%2};"       : "=l"(d) : "f"(x), "f"(y))
#define LG2(d,s)      asm("lg2.approx.f32 %0,%1;"     : "=f"(d) : "f"(s))
#define EX2(d,s)      asm("ex2.approx.f32 %0,%1;"     : "=f"(d) : "f"(s))
#define RCP(d,s)      asm("rcp.approx.f32 %0,%1;"     : "=f"(d) : "f"(s))

// s^(5/6); s==0 -> lg2=-Inf -> ex2=0 (matches guarded ref)
__device__ __forceinline__ float pow56(float s) {
    float l, r; LG2(l, s); l *= 0.8333333333f; EX2(r, l); return r;
}
// sd^(1/5); sd==0 -> 0
__device__ __forceinline__ float pow15(float sd) {
    float l, r; LG2(l, sd); l *= 0.2f; EX2(r, l); return r;
}

// one orientation: packed (s0,s1) = sum over 5 windows of relu(r)^6
// center-out build: 13 packed ops for all 5 windows (NC folded once)
__device__ __forceinline__ u64 orient_S(const float2* __restrict__ g,
                                        int base, int st, u64 NC, u64 Dc)
{
    const u64 NEG1 = 0xBF800000BF800000ULL;

    u64 D0 = *(const u64*)&g[base - 4 * st];
    u64 D1 = *(const u64*)&g[base - 3 * st];
    u64 D2 = *(const u64*)&g[base - 2 * st];
    u64 D3 = *(const u64*)&g[base - 1 * st];
    u64 D5 = *(const u64*)&g[base + 1 * st];
    u64 D6 = *(const u64*)&g[base + 2 * st];
    u64 D7 = *(const u64*)&g[base + 3 * st];
    u64 D8 = *(const u64*)&g[base + 4 * st];

    // R2 = d2+d3+d4+d5+d6 + NC  (window q=2)
    u64 pa, pb, R2;
    ADD2(pa, D2, D3); ADD2(pb, Dc, D5); ADD2(pa, pa, pb); ADD2(pa, pa, D6);
    ADD2(R2, pa, NC);
    // slides outward, 2 ops each
    u64 R0, R1, R3, R4;
    ADD2(R1, R2, D7); FMA2(R1, D2, NEG1, R1);   // q=1: 3..7
    ADD2(R0, R1, D8); FMA2(R0, D3, NEG1, R0);   // q=0: 4..8
    ADD2(R3, R2, D1); FMA2(R3, D6, NEG1, R3);   // q=3: 1..5
    ADD2(R4, R3, D0); FMA2(R4, D5, NEG1, R4);   // q=4: 0..4

    u64 S = 0ULL;
    // relu per 32-bit half via FMNMX (alu pipe); halves are separate regs, pack/unpack coalesced
    #define QSTEP(R) { float qa, qb; UNPK2(qa, qb, R); \
                       qa = fmaxf(qa, 0.f); qb = fmaxf(qb, 0.f); \
                       u64 T; PACK2(T, qa, qb); \
                       u64 T2; MUL2(T2, T, T); u64 T4; MUL2(T4, T2, T2); \
                       FMA2(S, T4, T2, S); }
    QSTEP(R0) QSTEP(R1) QSTEP(R2) QSTEP(R3) QSTEP(R4)
    #undef QSTEP
    return S;
}

__global__ __launch_bounds__(TPB, 6)   // 37-reg budget: let ptxas batch tap loads
void topo_kernel(const float* __restrict__ state, float* __restrict__ out, int nb)
{
    const int b   = blockIdx.x;
    const int tid = threadIdx.x;

    __shared__ float2 g[TCELLS];     // channel-combined, zero halo
    __shared__ float2 nc6[361];      // (-6x0,-6x1) on the raw 19x19 grid
    __shared__ float  red[64];

    for (int i = tid; i < TCELLS; i += TPB) g[i] = make_float2(0.f, 0.f);
    __syncthreads();

    const float* sp = state + (size_t)b * 1083;
    for (int i = tid; i < 361; i += TPB) {
        int y = i / 19, x = i - y * 19;
        float x0 = sp[3 * i], x1 = sp[3 * i + 1], x2 = sp[3 * i + 2];
        g[(y + 4) * TW + (x + 4)] =
            make_float2(fmaf(-5.f, x1 + x2, x0), fmaf(-5.f, x0 + x2, x1));
        nc6[i] = make_float2(-6.f * x0, -6.f * x1);
    }
    __syncthreads();

    // conflict-free lane->position mapping:
    //   tid <  272 : (py, px) = (tid>>4, tid&15)   -> warps cover 2x 128B chunks
    //   tid >= 272 : px = 16, py = tid-272         -> column, stride 232B (no conflicts)
    int py, px;
    if (tid < 272) { py = tid >> 4;  px = tid & 15; }
    else           { py = tid - 272; px = 16; }
    const int p    = py * 17 + px;               // logical position index 0..287
    const int base = (py + 5) * TW + (px + 5);
    const int steps[4] = {1, TW, TW + 1, TW - 1};   // H, V, diag, anti-diag

    float logit, dval;
    {
        const u64 NC = *(const u64*)&nc6[(py + 1) * 19 + (px + 1)];
        const u64 Dc = *(const u64*)&g[base];

        u64 Sa = orient_S(g, base, steps[0], NC, Dc);
        u64 Sb = orient_S(g, base, steps[1], NC, Dc);
        u64 Sc = orient_S(g, base, steps[2], NC, Dc);
        u64 Sd = orient_S(g, base, steps[3], NC, Dc);
        float a0, a1, b0, b1, c0, c1, d0, d1;
        UNPK2(a0, a1, Sa); UNPK2(b0, b1, Sb);
        UNPK2(c0, c1, Sc); UNPK2(d0, d1, Sd);
        float sd0 = (pow56(a0) + pow56(b0)) + (pow56(c0) + pow56(d0));
        float sd1 = (pow56(a1) + pow56(b1)) + (pow56(c1) + pow56(d1));
        float f0 = pow15(sd0);
        float f1 = pow15(sd1);
        logit = f0 + f1;
        dval  = f0 - f1;
    }

    const unsigned FULL = 0xffffffffu;
    const int wid  = tid >> 5;
    const int lane = tid & 31;

    // position 288 (py=px=16): one orientation each on lane 0 of warps 0..3
    if (lane == 0 && wid < 4) {
        const int b2 = 21 * TW + 21;
        const u64 NC2 = *(const u64*)&nc6[17 * 19 + 17];
        const u64 Dc2 = *(const u64*)&g[b2];
        u64 S = orient_S(g, b2, steps[wid], NC2, Dc2);
        float s0, s1; UNPK2(s0, s1, S);
        red[40 + 2 * wid]     = pow56(s0);
        red[40 + 2 * wid + 1] = pow56(s1);
    }

    // block max of logits
    float m = logit;
    #pragma unroll
    for (int off = 16; off; off >>= 1)
        m = fmaxf(m, __shfl_xor_sync(FULL, m, off));
    if (lane == 0) red[wid] = m;
    __syncthreads();

    float logit2 = -INFINITY, dval2 = 0.f;   // assembled by tid 0
    if (tid < 32) {
        float t = (tid < TPB / 32) ? red[tid] : -INFINITY;
        if (tid == 0) {
            float sd0 = (red[40] + red[42]) + (red[44] + red[46]);
            float sd1 = (red[41] + red[43]) + (red[45] + red[47]);
            float f0 = pow15(sd0);
            float f1 = pow15(sd1);
            logit2 = f0 + f1;
            dval2  = f0 - f1;
            t = fmaxf(t, logit2);
        }
        #pragma unroll
        for (int off = 8; off; off >>= 1)
            t = fmaxf(t, __shfl_xor_sync(FULL, t, off));
        if (tid == 0) red[32] = t;
    }
    __syncthreads();
    const float maxv = red[32];

    // exp(2*(l-maxv)) = ex2(C*(l-maxv)), C = 2*log2(e)
    const float C = 2.8853900817779268f;
    float e;  EX2(e,  C * (logit  - maxv));
    float e2 = 0.f;
    if (tid == 0) EX2(e2, C * (logit2 - maxv));

    float se = e + e2, sv = dval + dval2;
    #pragma unroll
    for (int off = 16; off; off >>= 1) {
        se += __shfl_xor_sync(FULL, se, off);
        sv += __shfl_xor_sync(FULL, sv, off);
    }
    if (lane == 0) { red[wid] = se; red[wid + 16] = sv; }
    __syncthreads();
    if (tid < 32) {
        float a  = (tid < TPB / 32) ? red[tid] : 0.f;
        float bb = (tid < TPB / 32) ? red[tid + 16] : 0.f;
        #pragma unroll
        for (int off = 8; off; off >>= 1) {
            a  += __shfl_xor_sync(FULL, a, off);
            bb += __shfl_xor_sync(FULL, bb, off);
        }
        if (tid == 0) { red[33] = a; red[34] = bb; }
    }
    __syncthreads();

    float rden; RCP(rden, red[33]);
    out[(size_t)b * NPOS + p] = e * rden;
    if (tid == 0) {
        out[(size_t)b * NPOS + 288] = e2 * rden;
        out[(size_t)nb * NPOS + b]  = tanhf(red[34] * (0.2f / 32.f)); // tanh(VS*VG*D)
    }
}

extern "C" void kernel_launch(void* const* d_in, const int* in_sizes, int n_in,
                              void* d_out, int out_size)
{
    const float* state = (const float*)d_in[0];
    const int nb = in_sizes[0] / (19 * 19 * 3);
    topo_kernel<<<nb, TPB>>>(state, (float*)d_out, nb);
}